// round 1
// baseline (speedup 1.0000x reference)
#include <cuda_runtime.h>

static constexpr int NODES = 50000;
static constexpr int EDGES = 400000;
static constexpr int DTOT  = 192;   // IN + POS
static constexpr int EMB   = 128;
static constexpr float LNE = 1e-5f;

// Scratch: aggregated concat(x,pos) per destination node. 38.4 MB.
__device__ float g_agg[(size_t)NODES * DTOT];

// ---------------------------------------------------------------------------
// Zero the aggregation buffer. Grid sized exactly: NODES*192/4 float4 = 2.4M.
// ---------------------------------------------------------------------------
__global__ __launch_bounds__(256) void zero_agg_kernel() {
    size_t i = (size_t)blockIdx.x * blockDim.x + threadIdx.x;
    ((float4*)g_agg)[i] = make_float4(0.f, 0.f, 0.f, 0.f);
}

// ---------------------------------------------------------------------------
// Edge scatter: one warp per edge. 192 features = 32 lanes x float4 (x part)
// + 16 lanes x float4 (pos part), via vector reductions (no return value).
// ---------------------------------------------------------------------------
__global__ __launch_bounds__(256) void scatter_kernel(const float* __restrict__ x,
                                                      const float* __restrict__ pos,
                                                      const int* __restrict__ ei) {
    int gw   = blockIdx.x * 8 + (threadIdx.x >> 5);
    int lane = threadIdx.x & 31;
    if (gw >= EDGES) return;
    int src = __ldg(ei + gw);
    int dst = __ldg(ei + EDGES + gw);

    float4 v = __ldg((const float4*)x + (size_t)src * 32 + lane);
    float* a = g_agg + (size_t)dst * DTOT + lane * 4;
    asm volatile("red.global.add.v4.f32 [%0], {%1, %2, %3, %4};"
                 :: "l"(a), "f"(v.x), "f"(v.y), "f"(v.z), "f"(v.w) : "memory");

    if (lane < 16) {
        float4 p = __ldg((const float4*)pos + (size_t)src * 16 + lane);
        float* ap = g_agg + (size_t)dst * DTOT + 128 + lane * 4;
        asm volatile("red.global.add.v4.f32 [%0], {%1, %2, %3, %4};"
                     :: "l"(ap), "f"(p.x), "f"(p.y), "f"(p.z), "f"(p.w) : "memory");
    }
}

// ---------------------------------------------------------------------------
// Fused GIN branch: per 64-row tile,
//   hin = (1+eps)*feat + agg           (staged transposed in smem, pad 65)
//   U   = relu(LN(hin @ W1 + b1))      (reg-blocked 4x8, W tiles in smem)
//   V   = U @ W2 + b2
//   out = relu(LN(V)) [+ x residual]
// DIN = 192 (branch 1, feat = concat(x,pos), residual) or 64 (branch 2, pos).
// ---------------------------------------------------------------------------
template<int DIN, bool RESID>
__global__ __launch_bounds__(256)
void gin_kernel(const float* __restrict__ x, const float* __restrict__ pos,
                const float* __restrict__ epsv,
                const float* __restrict__ W1, const float* __restrict__ b1,
                const float* __restrict__ g1, const float* __restrict__ be1,
                const float* __restrict__ W2, const float* __restrict__ b2,
                const float* __restrict__ lng, const float* __restrict__ lnb,
                float* __restrict__ out)
{
    extern __shared__ float smem[];
    constexpr int HROWS = (DIN > 128 ? DIN : 128);   // buffer also holds 128x64 U^T
    float* s_h = smem;                // [HROWS][65] transposed activations
    float* s_w = smem + HROWS * 65;   // [32][128] weight k-tile

    const int tid = threadIdx.x;
    const int tx  = tid & 15;         // 16 column groups of 8
    const int ty  = tid >> 4;         // 16 row groups of 4
    const int row0 = blockIdx.x * 64;
    const float e1 = 1.0f + __ldg(epsv);

    // ---- stage hin transposed: s_h[k][r] ----
    for (int idx = tid; idx < 64 * DIN; idx += 256) {
        int r = idx / DIN;
        int k = idx - r * DIN;
        int row = row0 + r;
        float v = 0.0f;
        if (row < NODES) {
            float nf;
            if (DIN == 192) nf = (k < 128) ? __ldg(x + (size_t)row * 128 + k)
                                           : __ldg(pos + (size_t)row * 64 + (k - 128));
            else            nf = __ldg(pos + (size_t)row * 64 + k);
            float ag = g_agg[(size_t)row * DTOT + (DIN == 192 ? k : 128 + k)];
            v = fmaf(e1, nf, ag);
        }
        s_h[k * 65 + r] = v;
    }
    __syncthreads();

    float acc[4][8];
#pragma unroll
    for (int i = 0; i < 4; i++)
#pragma unroll
        for (int c = 0; c < 8; c++) acc[i][c] = 0.0f;

    // ---- GEMM1: U = hin @ W1 ----
    for (int kt = 0; kt < DIN; kt += 32) {
        const float4* wg = (const float4*)(W1 + (size_t)kt * 128);
#pragma unroll
        for (int i = tid; i < 1024; i += 256)
            ((float4*)s_w)[i] = __ldg(wg + i);
        __syncthreads();
#pragma unroll
        for (int kk = 0; kk < 32; ++kk) {
            const float* hrow = s_h + (kt + kk) * 65 + (ty << 2);
            float h0 = hrow[0], h1 = hrow[1], h2 = hrow[2], h3 = hrow[3];
            const float* wrow = s_w + kk * 128 + (tx << 3);
            float w[8];
#pragma unroll
            for (int c = 0; c < 8; c++) w[c] = wrow[c];
#pragma unroll
            for (int c = 0; c < 8; c++) {
                acc[0][c] = fmaf(h0, w[c], acc[0][c]);
                acc[1][c] = fmaf(h1, w[c], acc[1][c]);
                acc[2][c] = fmaf(h2, w[c], acc[2][c]);
                acc[3][c] = fmaf(h3, w[c], acc[3][c]);
            }
        }
        __syncthreads();
    }

    // ---- epilogue 1: +b1, LayerNorm(g1,be1), relu -> U^T into s_h ----
    {
        float bv[8], gv[8], ev[8];
#pragma unroll
        for (int c = 0; c < 8; c++) {
            bv[c] = __ldg(b1  + (tx << 3) + c);
            gv[c] = __ldg(g1  + (tx << 3) + c);
            ev[c] = __ldg(be1 + (tx << 3) + c);
        }
#pragma unroll
        for (int ri = 0; ri < 4; ri++) {
            float s = 0.f, q = 0.f;
#pragma unroll
            for (int c = 0; c < 8; c++) {
                float u = acc[ri][c] + bv[c];
                acc[ri][c] = u;
                s += u;
                q = fmaf(u, u, q);
            }
#pragma unroll
            for (int o = 8; o >= 1; o >>= 1) {
                s += __shfl_xor_sync(0xffffffffu, s, o);
                q += __shfl_xor_sync(0xffffffffu, q, o);
            }
            float m    = s * (1.0f / 128.0f);
            float var  = fmaf(-m, m, q * (1.0f / 128.0f));
            float rstd = rsqrtf(var + LNE);
#pragma unroll
            for (int c = 0; c < 8; c++) {
                float u = (acc[ri][c] - m) * rstd;
                u = fmaf(u, gv[c], ev[c]);
                u = fmaxf(u, 0.0f);
                s_h[((tx << 3) + c) * 65 + (ty << 2) + ri] = u;
            }
        }
    }
    __syncthreads();

    // ---- GEMM2: V = U @ W2 ----
#pragma unroll
    for (int i = 0; i < 4; i++)
#pragma unroll
        for (int c = 0; c < 8; c++) acc[i][c] = 0.0f;

    for (int kt = 0; kt < 128; kt += 32) {
        const float4* wg = (const float4*)(W2 + (size_t)kt * 128);
#pragma unroll
        for (int i = tid; i < 1024; i += 256)
            ((float4*)s_w)[i] = __ldg(wg + i);
        __syncthreads();
#pragma unroll
        for (int kk = 0; kk < 32; ++kk) {
            const float* hrow = s_h + (kt + kk) * 65 + (ty << 2);
            float h0 = hrow[0], h1 = hrow[1], h2 = hrow[2], h3 = hrow[3];
            const float* wrow = s_w + kk * 128 + (tx << 3);
            float w[8];
#pragma unroll
            for (int c = 0; c < 8; c++) w[c] = wrow[c];
#pragma unroll
            for (int c = 0; c < 8; c++) {
                acc[0][c] = fmaf(h0, w[c], acc[0][c]);
                acc[1][c] = fmaf(h1, w[c], acc[1][c]);
                acc[2][c] = fmaf(h2, w[c], acc[2][c]);
                acc[3][c] = fmaf(h3, w[c], acc[3][c]);
            }
        }
        __syncthreads();
    }

    // ---- epilogue 2: +b2, LayerNorm(lng,lnb), relu, (+x), store ----
    {
        float bv[8], gv[8], ev[8];
#pragma unroll
        for (int c = 0; c < 8; c++) {
            bv[c] = __ldg(b2  + (tx << 3) + c);
            gv[c] = __ldg(lng + (tx << 3) + c);
            ev[c] = __ldg(lnb + (tx << 3) + c);
        }
#pragma unroll
        for (int ri = 0; ri < 4; ri++) {
            float s = 0.f, q = 0.f;
#pragma unroll
            for (int c = 0; c < 8; c++) {
                float u = acc[ri][c] + bv[c];
                acc[ri][c] = u;
                s += u;
                q = fmaf(u, u, q);
            }
#pragma unroll
            for (int o = 8; o >= 1; o >>= 1) {
                s += __shfl_xor_sync(0xffffffffu, s, o);
                q += __shfl_xor_sync(0xffffffffu, q, o);
            }
            float m    = s * (1.0f / 128.0f);
            float var  = fmaf(-m, m, q * (1.0f / 128.0f));
            float rstd = rsqrtf(var + LNE);

            int row = row0 + (ty << 2) + ri;
            if (row < NODES) {
                float vout[8];
#pragma unroll
                for (int c = 0; c < 8; c++) {
                    float u = (acc[ri][c] - m) * rstd;
                    u = fmaf(u, gv[c], ev[c]);
                    u = fmaxf(u, 0.0f);
                    if (RESID) u += __ldg(x + (size_t)row * 128 + (tx << 3) + c);
                    vout[c] = u;
                }
                float4* o = (float4*)(out + (size_t)row * 128 + (tx << 3));
                o[0] = make_float4(vout[0], vout[1], vout[2], vout[3]);
                o[1] = make_float4(vout[4], vout[5], vout[6], vout[7]);
            }
        }
    }
}

// ---------------------------------------------------------------------------
extern "C" void kernel_launch(void* const* d_in, const int* in_sizes, int n_in,
                              void* d_out, int out_size) {
    const float* x    = (const float*)d_in[0];
    const float* pos  = (const float*)d_in[1];
    const int*   ei   = (const int*)d_in[2];
    const float* eps  = (const float*)d_in[3];
    const float* W1   = (const float*)d_in[4];
    const float* b1   = (const float*)d_in[5];
    const float* g1   = (const float*)d_in[6];
    const float* be1  = (const float*)d_in[7];
    const float* W2   = (const float*)d_in[8];
    const float* b2   = (const float*)d_in[9];
    const float* lng  = (const float*)d_in[10];
    const float* lnb  = (const float*)d_in[11];
    const float* epsp = (const float*)d_in[12];
    const float* W1p  = (const float*)d_in[13];
    const float* b1p  = (const float*)d_in[14];
    const float* g1p  = (const float*)d_in[15];
    const float* be1p = (const float*)d_in[16];
    const float* W2p  = (const float*)d_in[17];
    const float* b2p  = (const float*)d_in[18];
    const float* lnpg = (const float*)d_in[19];
    const float* lnpb = (const float*)d_in[20];
    float* out = (float*)d_out;

    zero_agg_kernel<<<(NODES * DTOT / 4) / 256, 256>>>();
    scatter_kernel<<<EDGES / 8, 256>>>(x, pos, ei);

    const int grid = (NODES + 63) / 64;
    const size_t smem1 = (size_t)(192 * 65 + 32 * 128) * sizeof(float);  // 66304 B
    const size_t smem2 = (size_t)(128 * 65 + 32 * 128) * sizeof(float);  // 49664 B
    cudaFuncSetAttribute(gin_kernel<192, true>,
                         cudaFuncAttributeMaxDynamicSharedMemorySize, (int)smem1);
    cudaFuncSetAttribute(gin_kernel<64, false>,
                         cudaFuncAttributeMaxDynamicSharedMemorySize, (int)smem2);

    gin_kernel<192, true><<<grid, 256, smem1>>>(
        x, pos, eps, W1, b1, g1, be1, W2, b2, lng, lnb, out);
    gin_kernel<64, false><<<grid, 256, smem2>>>(
        x, pos, epsp, W1p, b1p, g1p, be1p, W2p, b2p, lnpg, lnpb,
        out + (size_t)NODES * EMB);
}

// round 5
// speedup vs baseline: 1.6427x; 1.6427x over previous
#include <cuda_runtime.h>
#include <cuda_bf16.h>
#include <cstdint>

static constexpr int NODES = 50000;
static constexpr int EDGES = 400000;
static constexpr float LNE = 1e-5f;

__device__ float g_agg[(size_t)NODES * 192];

// ---------------- smem layout (bytes) ----------------
static constexpr int PAR_OFF = 0;               // 768 floats (b1,g1,be1,b2,g2,be2)
static constexpr int RED_OFF = 3072;            // 256 float2 (LN partial sums)
static constexpr int AH_OFF  = 5120;            // A hi (max 128 x 400B)
static constexpr int AL_OFF  = AH_OFF + 51200;  // A lo
static constexpr int BH_OFF  = AL_OFF + 51200;  // B hi (max 192 x 272B)
static constexpr int BL_OFF  = BH_OFF + 52224;  // B lo
static constexpr int SM_TOTAL = BL_OFF + 52224; // 211968 B
static constexpr int SB = 272;                  // B row stride (128*2 + 16)
static constexpr int SU = 272;                  // U row stride

// ---------------- helpers ----------------
__device__ __forceinline__ uint32_t smem_u32(const void* p) {
    uint32_t a;
    asm("{ .reg .u64 t; cvta.to.shared.u64 t, %1; cvt.u32.u64 %0, t; }" : "=r"(a) : "l"(p));
    return a;
}
__device__ __forceinline__ void split2(float a, float b, uint32_t& hi, uint32_t& lo) {
    __nv_bfloat16 ah = __float2bfloat16_rn(a), bh = __float2bfloat16_rn(b);
    float ar = a - __bfloat162float(ah), br = b - __bfloat162float(bh);
    __nv_bfloat16 al = __float2bfloat16_rn(ar), bl = __float2bfloat16_rn(br);
    hi = (uint32_t)__bfloat16_as_ushort(ah) | ((uint32_t)__bfloat16_as_ushort(bh) << 16);
    lo = (uint32_t)__bfloat16_as_ushort(al) | ((uint32_t)__bfloat16_as_ushort(bl) << 16);
}
__device__ __forceinline__ void ldsm4(uint32_t* r, uint32_t addr) {
    asm volatile("ldmatrix.sync.aligned.m8n8.x4.shared.b16 {%0,%1,%2,%3}, [%4];"
                 : "=r"(r[0]), "=r"(r[1]), "=r"(r[2]), "=r"(r[3]) : "r"(addr));
}
__device__ __forceinline__ void ldsm4t(uint32_t* r, uint32_t addr) {
    asm volatile("ldmatrix.sync.aligned.m8n8.x4.trans.shared.b16 {%0,%1,%2,%3}, [%4];"
                 : "=r"(r[0]), "=r"(r[1]), "=r"(r[2]), "=r"(r[3]) : "r"(addr));
}
__device__ __forceinline__ void mma16816(float* d, const uint32_t* a, const uint32_t* b) {
    asm volatile("mma.sync.aligned.m16n8k16.row.col.f32.bf16.bf16.f32 "
                 "{%0,%1,%2,%3}, {%4,%5,%6,%7}, {%8,%9}, {%0,%1,%2,%3};"
                 : "+f"(d[0]), "+f"(d[1]), "+f"(d[2]), "+f"(d[3])
                 : "r"(a[0]), "r"(a[1]), "r"(a[2]), "r"(a[3]), "r"(b[0]), "r"(b[1]));
}

// 3-pass bf16-split GEMM: D[128x128] += A[128xK] * B[KxN=128]
__device__ __forceinline__ void gemm3(float acc[2][8][4], uint32_t sbase,
                                      int sa, int ksteps, int m0, int n0, int lane)
{
    const uint32_t aoff = (uint32_t)((lane & 15) * sa + (lane >> 4) * 16);
    const uint32_t boff = (uint32_t)((lane & 15) * SB + (lane >> 4) * 16);
    for (int pass = 0; pass < 3; pass++) {
        uint32_t aAddr = sbase + ((pass == 1) ? AL_OFF : AH_OFF) + m0 * sa + aoff;
        uint32_t bAddr = sbase + ((pass == 2) ? BL_OFF : BH_OFF) + n0 * 2 + boff;
        for (int ks = 0; ks < ksteps; ks++) {
            uint32_t a0[4], a1[4], bf[8][2], r[4];
            ldsm4(a0, aAddr);
            ldsm4(a1, aAddr + 16 * sa);
#pragma unroll
            for (int bt = 0; bt < 4; bt++) {
                ldsm4t(r, bAddr + bt * 32);
                bf[2 * bt][0] = r[0]; bf[2 * bt][1] = r[1];
                bf[2 * bt + 1][0] = r[2]; bf[2 * bt + 1][1] = r[3];
            }
#pragma unroll
            for (int nt = 0; nt < 8; nt++) {
                mma16816(acc[0][nt], a0, bf[nt]);
                mma16816(acc[1][nt], a1, bf[nt]);
            }
            aAddr += 32;       // 16 k-cols * 2B
            bAddr += 16 * SB;  // 16 k-rows
        }
    }
}

// stage weights W[rows][128] -> B hi/lo smem
__device__ __forceinline__ void stage_w(char* smem, const float* __restrict__ W,
                                        int rows, int tid)
{
    for (int idx = tid; idx < rows * 32; idx += 256) {
        int k = idx >> 5, c = (idx & 31) * 4;
        float4 w = __ldg((const float4*)(W + (size_t)k * 128 + c));
        uint32_t h0, l0, h1, l1;
        split2(w.x, w.y, h0, l0);
        split2(w.z, w.w, h1, l1);
        char* p = smem + BH_OFF + k * SB + c * 2;
        *(uint32_t*)p = h0; *(uint32_t*)(p + 4) = h1;
        char* q = p + (BL_OFF - BH_OFF);
        *(uint32_t*)q = l0; *(uint32_t*)(q + 4) = l1;
    }
}

// bias add + LN stats (cross-half via smem); leaves biased values in acc
__device__ __forceinline__ void ln_stats(float acc[2][8][4], char* smem,
                                         const float* s_par, int parOff,
                                         int m0, int n0, int cg, int lane,
                                         float mean[2][2], float rstd[2][2])
{
    float2* s_red = (float2*)(smem + RED_OFF);
    const int grp = lane >> 2, qd = lane & 3;
#pragma unroll
    for (int mt = 0; mt < 2; mt++) {
        float sA = 0.f, qA = 0.f, sB = 0.f, qB = 0.f;
#pragma unroll
        for (int nt = 0; nt < 8; nt++) {
            int n = n0 + nt * 8 + qd * 2;
            float b0v = s_par[parOff + n], b1v = s_par[parOff + n + 1];
            float d0 = acc[mt][nt][0] + b0v, d1 = acc[mt][nt][1] + b1v;
            float d2 = acc[mt][nt][2] + b0v, d3 = acc[mt][nt][3] + b1v;
            acc[mt][nt][0] = d0; acc[mt][nt][1] = d1;
            acc[mt][nt][2] = d2; acc[mt][nt][3] = d3;
            sA += d0 + d1; qA = fmaf(d0, d0, fmaf(d1, d1, qA));
            sB += d2 + d3; qB = fmaf(d2, d2, fmaf(d3, d3, qB));
        }
#pragma unroll
        for (int o = 1; o <= 2; o <<= 1) {
            sA += __shfl_xor_sync(~0u, sA, o); qA += __shfl_xor_sync(~0u, qA, o);
            sB += __shfl_xor_sync(~0u, sB, o); qB += __shfl_xor_sync(~0u, qB, o);
        }
        if (qd == 0) {
            int rA = m0 + mt * 16 + grp;
            s_red[cg * 128 + rA]     = make_float2(sA, qA);
            s_red[cg * 128 + rA + 8] = make_float2(sB, qB);
        }
    }
    __syncthreads();
#pragma unroll
    for (int mt = 0; mt < 2; mt++)
#pragma unroll
        for (int h = 0; h < 2; h++) {
            int r = m0 + mt * 16 + grp + h * 8;
            float2 t0 = s_red[r], t1 = s_red[128 + r];
            float mu = (t0.x + t1.x) * (1.0f / 128.0f);
            float var = fmaf(-mu, mu, (t0.y + t1.y) * (1.0f / 128.0f));
            mean[mt][h] = mu;
            rstd[mt][h] = rsqrtf(var + LNE);
        }
}

// ---------------- aux kernels ----------------
__global__ __launch_bounds__(256) void zero_agg_kernel() {
    size_t i = (size_t)blockIdx.x * blockDim.x + threadIdx.x;
    ((float4*)g_agg)[i] = make_float4(0.f, 0.f, 0.f, 0.f);
}

__global__ __launch_bounds__(256) void scatter_kernel(const float* __restrict__ x,
                                                      const float* __restrict__ pos,
                                                      const int* __restrict__ ei) {
    int gw   = blockIdx.x * 8 + (threadIdx.x >> 5);
    int lane = threadIdx.x & 31;
    if (gw >= EDGES) return;
    int src = __ldg(ei + gw);
    int dst = __ldg(ei + EDGES + gw);

    float4 v = __ldg((const float4*)x + (size_t)src * 32 + lane);
    float* a = g_agg + (size_t)dst * 192 + lane * 4;
    asm volatile("red.global.add.v4.f32 [%0], {%1, %2, %3, %4};"
                 :: "l"(a), "f"(v.x), "f"(v.y), "f"(v.z), "f"(v.w) : "memory");
    if (lane < 16) {
        float4 p = __ldg((const float4*)pos + (size_t)src * 16 + lane);
        float* ap = g_agg + (size_t)dst * 192 + 128 + lane * 4;
        asm volatile("red.global.add.v4.f32 [%0], {%1, %2, %3, %4};"
                     :: "l"(ap), "f"(p.x), "f"(p.y), "f"(p.z), "f"(p.w) : "memory");
    }
}

// ---------------- fused HMMA GIN (both branches via blockIdx.y) ----------------
__global__ __launch_bounds__(256, 1)
void gin_mma_kernel(const float* __restrict__ x, const float* __restrict__ pos,
                    const float* __restrict__ eps,  const float* __restrict__ W1,
                    const float* __restrict__ b1,   const float* __restrict__ g1,
                    const float* __restrict__ be1,  const float* __restrict__ W2,
                    const float* __restrict__ b2,   const float* __restrict__ lng,
                    const float* __restrict__ lnb,
                    const float* __restrict__ epsp, const float* __restrict__ W1p,
                    const float* __restrict__ b1p,  const float* __restrict__ g1p,
                    const float* __restrict__ be1p, const float* __restrict__ W2p,
                    const float* __restrict__ b2p,  const float* __restrict__ lnpg,
                    const float* __restrict__ lnpb,
                    float* __restrict__ out)
{
    extern __shared__ char smem[];
    const uint32_t sbase = smem_u32(smem);
    float* s_par = (float*)smem;
    const int tid = threadIdx.x, lane = tid & 31, wid = tid >> 5;
    const int m0 = (wid & 3) * 32, n0 = (wid >> 2) * 64, cg = wid >> 2;
    const int br = blockIdx.y;
    const int row0 = blockIdx.x * 128;

    const int din = br ? 64 : 192;
    const int sa1 = br ? 144 : 400;   // A row stride (din*2 + 16)
    const int ks1 = br ? 4 : 12;
    const float e1 = 1.0f + __ldg(br ? epsp : eps);
    const float* Wa = br ? W1p : W1;
    const float* Wb = br ? W2p : W2;
    float* outb = out + (br ? (size_t)NODES * 128 : 0);

    // stage LN / bias params
    {
        const float* pars[6] = { br ? b1p : b1, br ? g1p : g1, br ? be1p : be1,
                                 br ? b2p : b2, br ? lnpg : lng, br ? lnpb : lnb };
        for (int j = tid; j < 768; j += 256) s_par[j] = __ldg(pars[j >> 7] + (j & 127));
    }

    // stage A1 = (1+eps)*feat + agg   (bf16 hi/lo)
    {
        const int nf4 = din / 4;
        for (int idx = tid; idx < 128 * nf4; idx += 256) {
            int r = idx / nf4, c = (idx - r * nf4) * 4;
            int row = row0 + r;
            float4 f = make_float4(0.f, 0.f, 0.f, 0.f), a = f;
            if (row < NODES) {
                if (br == 0) {
                    f = (c < 128) ? __ldg((const float4*)(x + (size_t)row * 128 + c))
                                  : __ldg((const float4*)(pos + (size_t)row * 64 + (c - 128)));
                    a = __ldg((const float4*)(g_agg + (size_t)row * 192 + c));
                } else {
                    f = __ldg((const float4*)(pos + (size_t)row * 64 + c));
                    a = __ldg((const float4*)(g_agg + (size_t)row * 192 + 128 + c));
                }
            }
            float v0 = fmaf(e1, f.x, a.x), v1 = fmaf(e1, f.y, a.y);
            float v2 = fmaf(e1, f.z, a.z), v3 = fmaf(e1, f.w, a.w);
            uint32_t h0, l0, h1, l1;
            split2(v0, v1, h0, l0);
            split2(v2, v3, h1, l1);
            char* p = smem + AH_OFF + r * sa1 + c * 2;
            *(uint32_t*)p = h0; *(uint32_t*)(p + 4) = h1;
            char* q = p + (AL_OFF - AH_OFF);
            *(uint32_t*)q = l0; *(uint32_t*)(q + 4) = l1;
        }
    }
    stage_w(smem, Wa, din, tid);
    __syncthreads();

    // ---- GEMM1 ----
    float acc[2][8][4];
#pragma unroll
    for (int mt = 0; mt < 2; mt++)
#pragma unroll
        for (int nt = 0; nt < 8; nt++)
#pragma unroll
            for (int c = 0; c < 4; c++) acc[mt][nt][c] = 0.f;

    gemm3(acc, sbase, sa1, ks1, m0, n0, lane);
    __syncthreads();   // A/B regions free for reuse

    // ---- epilogue 1: LN + relu -> U (bf16 hi/lo in A region, stride 272) ----
    float mean[2][2], rstd[2][2];
    ln_stats(acc, smem, s_par, 0, m0, n0, cg, lane, mean, rstd);
    {
        const int grp = lane >> 2, qd = lane & 3;
#pragma unroll
        for (int mt = 0; mt < 2; mt++)
#pragma unroll
            for (int h = 0; h < 2; h++) {
                int r = m0 + mt * 16 + grp + h * 8;
                float mu = mean[mt][h], rs = rstd[mt][h];
#pragma unroll
                for (int nt = 0; nt < 8; nt++) {
                    int n = n0 + nt * 8 + qd * 2;
                    int ci = h * 2;
                    float d0 = acc[mt][nt][ci], d1 = acc[mt][nt][ci + 1];
                    float v0 = fmaf((d0 - mu) * rs, s_par[128 + n], s_par[256 + n]);
                    float v1 = fmaf((d1 - mu) * rs, s_par[128 + n + 1], s_par[256 + n + 1]);
                    v0 = fmaxf(v0, 0.f); v1 = fmaxf(v1, 0.f);
                    uint32_t hi, lo;
                    split2(v0, v1, hi, lo);
                    char* p = smem + AH_OFF + r * SU + n * 2;
                    *(uint32_t*)p = hi;
                    *(uint32_t*)(p + (AL_OFF - AH_OFF)) = lo;
                }
            }
    }
    stage_w(smem, Wb, 128, tid);
    __syncthreads();

    // ---- GEMM2 ----
#pragma unroll
    for (int mt = 0; mt < 2; mt++)
#pragma unroll
        for (int nt = 0; nt < 8; nt++)
#pragma unroll
            for (int c = 0; c < 4; c++) acc[mt][nt][c] = 0.f;

    gemm3(acc, sbase, SU, 8, m0, n0, lane);

    // ---- epilogue 2: LN + relu (+ residual) -> out ----
    ln_stats(acc, smem, s_par, 384, m0, n0, cg, lane, mean, rstd);
    {
        const int grp = lane >> 2, qd = lane & 3;
#pragma unroll
        for (int mt = 0; mt < 2; mt++)
#pragma unroll
            for (int h = 0; h < 2; h++) {
                int r = m0 + mt * 16 + grp + h * 8;
                int row = row0 + r;
                if (row >= NODES) continue;
                float mu = mean[mt][h], rs = rstd[mt][h];
#pragma unroll
                for (int nt = 0; nt < 8; nt++) {
                    int n = n0 + nt * 8 + qd * 2;
                    int ci = h * 2;
                    float d0 = acc[mt][nt][ci], d1 = acc[mt][nt][ci + 1];
                    float v0 = fmaf((d0 - mu) * rs, s_par[512 + n], s_par[640 + n]);
                    float v1 = fmaf((d1 - mu) * rs, s_par[512 + n + 1], s_par[640 + n + 1]);
                    v0 = fmaxf(v0, 0.f); v1 = fmaxf(v1, 0.f);
                    if (br == 0) {
                        float2 xv = *(const float2*)(x + (size_t)row * 128 + n);
                        v0 += xv.x; v1 += xv.y;
                    }
                    *(float2*)(outb + (size_t)row * 128 + n) = make_float2(v0, v1);
                }
            }
    }
}

// ---------------- launch ----------------
extern "C" void kernel_launch(void* const* d_in, const int* in_sizes, int n_in,
                              void* d_out, int out_size) {
    const float* x    = (const float*)d_in[0];
    const float* pos  = (const float*)d_in[1];
    const int*   ei   = (const int*)d_in[2];
    const float* eps  = (const float*)d_in[3];
    const float* W1   = (const float*)d_in[4];
    const float* b1   = (const float*)d_in[5];
    const float* g1   = (const float*)d_in[6];
    const float* be1  = (const float*)d_in[7];
    const float* W2   = (const float*)d_in[8];
    const float* b2   = (const float*)d_in[9];
    const float* lng  = (const float*)d_in[10];
    const float* lnb  = (const float*)d_in[11];
    const float* epsp = (const float*)d_in[12];
    const float* W1p  = (const float*)d_in[13];
    const float* b1p  = (const float*)d_in[14];
    const float* g1p  = (const float*)d_in[15];
    const float* be1p = (const float*)d_in[16];
    const float* W2p  = (const float*)d_in[17];
    const float* b2p  = (const float*)d_in[18];
    const float* lnpg = (const float*)d_in[19];
    const float* lnpb = (const float*)d_in[20];
    float* out = (float*)d_out;

    zero_agg_kernel<<<(NODES * 192 / 4) / 256, 256>>>();
    scatter_kernel<<<EDGES / 8, 256>>>(x, pos, ei);

    cudaFuncSetAttribute(gin_mma_kernel,
                         cudaFuncAttributeMaxDynamicSharedMemorySize, SM_TOTAL);
    dim3 grid((NODES + 127) / 128, 2);
    gin_mma_kernel<<<grid, 256, SM_TOTAL>>>(
        x, pos, eps, W1, b1, g1, be1, W2, b2, lng, lnb,
        epsp, W1p, b1p, g1p, be1p, W2p, b2p, lnpg, lnpb, out);
}